// round 3
// baseline (speedup 1.0000x reference)
#include <cuda_runtime.h>
#include <cstdint>

#define B_      256
#define SEQ_    128
#define HID_    1024
#define NB_     256
#define NL_     3
#define G_      8              // k-values per CTA (processed sequentially)
#define CHUNKS_ 16             // b-chunks (split softmax)
#define BPC_    (B_/CHUNKS_)   // 16 b per chunk

// Scratch (static device arrays only — no cudaMalloc allowed)
__device__ float g_part_u[NB_][CHUNKS_][HID_];   // 16 MB
__device__ float g_part_m[NB_][CHUNKS_];
__device__ float g_part_z[NB_][CHUNKS_];
__device__ float g_u[NB_][HID_];                 // 1 MB
__device__ float g_RH[NL_][HID_];                // R_w @ H_w  (3 x 1024)
__device__ float g_act[B_][HID_];                // slow-path activations
__device__ int   g_flag;                         // 1 iff alpha == 1 everywhere

// ---- cp.async helpers -------------------------------------------------------
__device__ __forceinline__ uint32_t smem_u32(const void* p) {
    return (uint32_t)__cvta_generic_to_shared(p);
}
__device__ __forceinline__ void cp_async16(uint32_t dst, const void* src) {
    asm volatile("cp.async.cg.shared.global [%0], [%1], 16;\n" :: "r"(dst), "l"(src));
}
__device__ __forceinline__ void cp_commit() {
    asm volatile("cp.async.commit_group;\n" ::: "memory");
}
template <int N>
__device__ __forceinline__ void cp_wait() {
    asm volatile("cp.async.wait_group %0;\n" :: "n"(N) : "memory");
}

// ---------------------------------------------------------------------------
// K1 (SMEM-staged): CTA handles (k-group of 8, b-chunk of 16).
//  - x tile (16 rows x 1024 f32 = 64 KB) staged once.
//  - S tiles (16 rows x 1024 f32 = 64 KB per k) double-buffered via cp.async.
//  - Per k: chunk-local softmax (all 16 scores first, then weighted sum).
// Dynamic SMEM = 64 + 128 KB (+ scores). 256 threads, tiny register footprint.
// ---------------------------------------------------------------------------
extern __shared__ float s_dyn[];

__global__ __launch_bounds__(256) void k1_partials(
    const float* __restrict__ ee, const float* __restrict__ S)
{
    float* sx = s_dyn;                  // [16][1024]  x tile
    float* ss = s_dyn + 16 * HID_;      // [2][16][1024] S double buffer
    float* sc = s_dyn + 48 * HID_;      // [16] scores

    const int t     = threadIdx.x;
    const int w     = t >> 5;
    const int lane  = t & 31;
    const int kbase = blockIdx.x * G_;
    const int c     = blockIdx.y;
    const int b0    = c * BPC_;
    const int h4    = t * 4;

    // group 0: x tile + S tile for k0
    {
        const uint32_t dst_x = smem_u32(sx + h4);
#pragma unroll
        for (int r = 0; r < BPC_; r++)
            cp_async16(dst_x + r * HID_ * 4,
                       ee + ((size_t)(b0 + r) * SEQ_) * HID_ + h4);
        const uint32_t dst_s = smem_u32(ss + h4);
#pragma unroll
        for (int r = 0; r < BPC_; r++)
            cp_async16(dst_s + r * HID_ * 4,
                       S + ((size_t)(b0 + r) * NB_ + kbase) * HID_ + h4);
    }
    cp_commit();
    // group 1: S tile for k1
    {
        const uint32_t dst_s = smem_u32(ss + 16 * HID_ + h4);
#pragma unroll
        for (int r = 0; r < BPC_; r++)
            cp_async16(dst_s + r * HID_ * 4,
                       S + ((size_t)(b0 + r) * NB_ + kbase + 1) * HID_ + h4);
    }
    cp_commit();

    for (int g = 0; g < G_; g++) {
        if (g + 1 < G_) cp_wait<1>(); else cp_wait<0>();
        __syncthreads();

        float* scur = ss + (g & 1) * 16 * HID_;

        // ---- scores: warp w computes dots for b = 2w, 2w+1 ----
        {
            const int bA = 2 * w, bB = 2 * w + 1;
            float dA = 0.f, dB = 0.f;
#pragma unroll
            for (int j = 0; j < 8; j++) {
                const int off = j * 128 + lane * 4;
                const float4 xA = *(const float4*)(sx + bA * HID_ + off);
                const float4 sA = *(const float4*)(scur + bA * HID_ + off);
                const float4 xB = *(const float4*)(sx + bB * HID_ + off);
                const float4 sB = *(const float4*)(scur + bB * HID_ + off);
                dA += xA.x * sA.x + xA.y * sA.y + xA.z * sA.z + xA.w * sA.w;
                dB += xB.x * sB.x + xB.y * sB.y + xB.z * sB.z + xB.w * sB.w;
            }
#pragma unroll
            for (int off = 16; off > 0; off >>= 1) {
                dA += __shfl_xor_sync(0xffffffffu, dA, off);
                dB += __shfl_xor_sync(0xffffffffu, dB, off);
            }
            if (lane == 0) { sc[bA] = dA; sc[bB] = dB; }
        }
        __syncthreads();

        // ---- weights (redundant per-thread; pure ALU) ----
        float scl[BPC_];
#pragma unroll
        for (int b = 0; b < BPC_; b++) scl[b] = sc[b];
        float m = scl[0];
#pragma unroll
        for (int b = 1; b < BPC_; b++) m = fmaxf(m, scl[b]);
        float z = 0.f;
        float wgt[BPC_];
#pragma unroll
        for (int b = 0; b < BPC_; b++) { wgt[b] = __expf(scl[b] - m); z += wgt[b]; }

        // ---- accumulate: thread owns h4 ----
        float4 acc = make_float4(0.f, 0.f, 0.f, 0.f);
#pragma unroll
        for (int b = 0; b < BPC_; b++) {
            const float4 sv = *(const float4*)(scur + b * HID_ + h4);
            acc.x += wgt[b] * sv.x;
            acc.y += wgt[b] * sv.y;
            acc.z += wgt[b] * sv.z;
            acc.w += wgt[b] * sv.w;
        }
        const int k = kbase + g;
        *(float4*)&g_part_u[k][c][h4] = acc;
        if (t == 0) { g_part_m[k][c] = m; g_part_z[k][c] = z; }

        __syncthreads();   // everyone done reading scur before it is refilled

        // prefetch S tile for k = kbase + g + 2 into the buffer just freed
        if (g + 2 < G_) {
            const uint32_t dst_s = smem_u32(scur + h4);
#pragma unroll
            for (int r = 0; r < BPC_; r++)
                cp_async16(dst_s + r * HID_ * 4,
                           S + ((size_t)(b0 + r) * NB_ + kbase + g + 2) * HID_ + h4);
            cp_commit();
        }
    }
}

// ---------------------------------------------------------------------------
// KMIX: blocks 0..255 combine split-softmax partials into u[k][:]
//       (block 0 also computes the alpha==1 flag);
//       blocks 256..258 compute RH[l][:] = R_w[l] @ H_w.
// ---------------------------------------------------------------------------
__global__ __launch_bounds__(256) void kmix(
    const float* __restrict__ alpha, const float* __restrict__ Rw,
    const float* __restrict__ Hw)
{
    const int bid = blockIdx.x;
    const int t = threadIdx.x;

    if (bid < NB_) {
        const int k = bid;
        const int h4 = t * 4;

        if (k == 0) {
            int ok = 1;
#pragma unroll
            for (int r = 0; r < 4; r++) ok &= (alpha[h4 + r] == 1.0f);
            ok = __syncthreads_and(ok);
            if (t == 0) g_flag = ok;
        }

        float m = -3.0e38f;
#pragma unroll
        for (int c = 0; c < CHUNKS_; c++) m = fmaxf(m, g_part_m[k][c]);
        float Z = 0.f, w[CHUNKS_];
#pragma unroll
        for (int c = 0; c < CHUNKS_; c++) {
            w[c] = __expf(g_part_m[k][c] - m);
            Z += g_part_z[k][c] * w[c];
        }
        const float inv = 1.f / Z;
        float4 s = make_float4(0.f, 0.f, 0.f, 0.f);
#pragma unroll
        for (int c = 0; c < CHUNKS_; c++) {
            const float4 p = *(const float4*)&g_part_u[k][c][h4];
            const float ww = w[c] * inv;
            s.x += ww * p.x; s.y += ww * p.y; s.z += ww * p.z; s.w += ww * p.w;
        }
        *(float4*)&g_u[k][h4] = s;
    } else {
        const int l = bid - NB_;
        const int j4 = t * 4;
        float4 s = make_float4(0.f, 0.f, 0.f, 0.f);
#pragma unroll 8
        for (int h = 0; h < HID_; h++) {
            const float r = __ldg(Rw + l * HID_ + h);
            const float4 hv = *(const float4*)(Hw + (size_t)h * HID_ + j4);
            s.x += r * hv.x; s.y += r * hv.y; s.z += r * hv.z; s.w += r * hv.w;
        }
        *(float4*)&g_RH[l][j4] = s;
    }
}

// ---------------------------------------------------------------------------
// Fast path (alpha == 1): out[i][l] = x[i]·R_w[l] + u[i]·RH[l]
// ---------------------------------------------------------------------------
__global__ __launch_bounds__(256) void k_fast(
    const float* __restrict__ ee, const float* __restrict__ Rw,
    float* __restrict__ out)
{
    if (!g_flag) return;
    const int w = (blockIdx.x * 256 + threadIdx.x) >> 5;
    if (w >= B_ * NL_) return;
    const int i = w / NL_;
    const int l = w % NL_;
    const int lane = threadIdx.x & 31;
    const float* xr = ee + (size_t)i * SEQ_ * HID_;
    float s = 0.f;
#pragma unroll
    for (int j0 = 0; j0 < HID_; j0 += 128) {
        const int j = j0 + lane * 4;
        const float4 xv = *(const float4*)(xr + j);
        const float4 rv = *(const float4*)(Rw + l * HID_ + j);
        const float4 uv = *(const float4*)&g_u[i][j];
        const float4 gv = *(const float4*)&g_RH[l][j];
        s += xv.x * rv.x + xv.y * rv.y + xv.z * rv.z + xv.w * rv.w
           + uv.x * gv.x + uv.y * gv.y + uv.z * gv.z + uv.w * gv.w;
    }
#pragma unroll
    for (int off = 16; off > 0; off >>= 1)
        s += __shfl_xor_sync(0xffffffffu, s, off);
    if (lane == 0) out[i * NL_ + l] = s;
}

// ---------------------------------------------------------------------------
// Slow path (general alpha): v = x + u@H^T, act = PReLU(v) -> g_act.
// ---------------------------------------------------------------------------
__global__ __launch_bounds__(256) void k3_full(
    const float* __restrict__ ee, const float* __restrict__ Hw,
    const float* __restrict__ alpha)
{
    if (g_flag) return;
    __shared__ float Us[32][33];
    __shared__ float Hs[32][33];
    const int t  = threadIdx.x;
    const int tx = t & 15, ty = t >> 4;
    const int i0 = blockIdx.x * 32, h0 = blockIdx.y * 32;
    const int lr = t >> 3;
    const int lc = (t & 7) * 4;
    float acc00 = 0.f, acc01 = 0.f, acc10 = 0.f, acc11 = 0.f;

    for (int kk = 0; kk < HID_; kk += 32) {
        const float4 uu = *(const float4*)&g_u[i0 + lr][kk + lc];
        const float4 hh = *(const float4*)(Hw + (size_t)(h0 + lr) * HID_ + kk + lc);
        Us[lr][lc] = uu.x; Us[lr][lc+1] = uu.y; Us[lr][lc+2] = uu.z; Us[lr][lc+3] = uu.w;
        Hs[lr][lc] = hh.x; Hs[lr][lc+1] = hh.y; Hs[lr][lc+2] = hh.z; Hs[lr][lc+3] = hh.w;
        __syncthreads();
#pragma unroll
        for (int j = 0; j < 32; j++) {
            const float a0 = Us[ty*2][j],   a1 = Us[ty*2+1][j];
            const float b0 = Hs[tx*2][j],   b1 = Hs[tx*2+1][j];
            acc00 += a0*b0; acc01 += a0*b1; acc10 += a1*b0; acc11 += a1*b1;
        }
        __syncthreads();
    }
    const float accs[2][2] = { {acc00, acc01}, {acc10, acc11} };
#pragma unroll
    for (int ii = 0; ii < 2; ii++)
#pragma unroll
        for (int jj = 0; jj < 2; jj++) {
            const int i = i0 + ty*2 + ii;
            const int h = h0 + tx*2 + jj;
            const float v = accs[ii][jj] + ee[(size_t)i * SEQ_ * HID_ + h];
            g_act[i][h] = (v >= 0.f) ? v : alpha[h] * v;
        }
}

__global__ __launch_bounds__(256) void k4_full(
    const float* __restrict__ Rw, float* __restrict__ out)
{
    if (g_flag) return;
    const int w = (blockIdx.x * 256 + threadIdx.x) >> 5;
    if (w >= B_ * NL_) return;
    const int i = w / NL_;
    const int l = w % NL_;
    const int lane = threadIdx.x & 31;
    float s = 0.f;
#pragma unroll 8
    for (int j = lane; j < HID_; j += 32)
        s += g_act[i][j] * Rw[l * HID_ + j];
#pragma unroll
    for (int off = 16; off > 0; off >>= 1)
        s += __shfl_xor_sync(0xffffffffu, s, off);
    if (lane == 0) out[i * NL_ + l] = s;
}

// ---------------------------------------------------------------------------
extern "C" void kernel_launch(void* const* d_in, const int* in_sizes, int n_in,
                              void* d_out, int out_size)
{
    const float* ee = (const float*)d_in[0];   // (256,128,1024)
    const float* S  = (const float*)d_in[1];   // (256, 256*1024)
    const float* Hw = (const float*)d_in[2];   // (1024,1024)
    const float* Rw = (const float*)d_in[3];   // (3,1024)
    const float* al = (const float*)d_in[4];   // (1024,)
    float* out = (float*)d_out;                // (256,3)

    const int smem_bytes = (48 * HID_ + 64) * sizeof(float);  // x + 2*S + scores
    cudaFuncSetAttribute(k1_partials,
                         cudaFuncAttributeMaxDynamicSharedMemorySize, smem_bytes);

    k1_partials<<<dim3(NB_ / G_, CHUNKS_), 256, smem_bytes>>>(ee, S);
    kmix<<<NB_ + NL_, 256>>>(al, Rw, Hw);
    k3_full<<<dim3(B_ / 32, HID_ / 32), 256>>>(ee, Hw, al);
    k4_full<<<(B_ * NL_ * 32) / 256, 256>>>(Rw, out);
    k_fast<<<(B_ * NL_ * 32) / 256, 256>>>(ee, Rw, out);
}